// round 6
// baseline (speedup 1.0000x reference)
#include <cuda_runtime.h>
#include <math.h>

// Problem dims
#define SS 512
#define BB 64
#define II 512
#define HH 1024
#define BH (BB*HH)

// Recurrent decomposition: 8 n-tiles (128 cols) x 16 k-chunks (64 k) = 128 blocks
#define NT 8
#define KC 16
#define NB (NT*KC)
#define ASP 68          // As row pitch (floats), mult of 4, conflict-free staging

// -------------------- device scratch --------------------------------------------
__device__ float g_pre[SS*BH];            // V x_t + b_V + b_W
__device__ float g_part2[2][KC][BH];      // parity-buffered split-K partials (8 MB)
__device__ unsigned g_aflag[NB];          // A(s) done -> aflag = s
__device__ unsigned g_bflag[NB];          // h_s written -> bflag = s+1
__device__ unsigned g_bar_cnt = 0;
__device__ volatile unsigned g_bar_gen = 0;

// -------------------- packed f32x2 helpers --------------------------------------
typedef unsigned long long u64;

__device__ __forceinline__ u64 pack2s(float x) {
    u64 r; asm("mov.b64 %0, {%1, %1};" : "=l"(r) : "f"(x)); return r;
}
__device__ __forceinline__ u64 fma2(u64 a, u64 b, u64 c) {
    u64 d; asm("fma.rn.f32x2 %0, %1, %2, %3;" : "=l"(d) : "l"(a), "l"(b), "l"(c));
    return d;
}
__device__ __forceinline__ float2 unpack2(u64 v) {
    float2 f; asm("mov.b64 {%0, %1}, %2;" : "=f"(f.x), "=f"(f.y) : "l"(v)); return f;
}
__device__ __forceinline__ float tanh_fast(float x) {
    float y; asm("tanh.approx.f32 %0, %1;" : "=f"(y) : "f"(x)); return y;
}

// flag ops
__device__ __forceinline__ void flag_set(unsigned* p, unsigned v) {
    asm volatile("st.release.gpu.global.b32 [%0], %1;" :: "l"(p), "r"(v) : "memory");
}
__device__ __forceinline__ void flag_wait_ge(const unsigned* p, unsigned v) {
    unsigned x;
    do {
        asm volatile("ld.acquire.gpu.global.b32 %0, [%1];" : "=r"(x) : "l"(p) : "memory");
    } while ((int)x < (int)v);
}

// one-time startup grid barrier (ticket; proven in R1/R2)
__device__ __forceinline__ void grid_sync_once() {
    __syncthreads();
    __threadfence();
    if (threadIdx.x == 0) {
        unsigned gen = g_bar_gen;
        if (atomicAdd(&g_bar_cnt, 1u) == NB - 1u) {
            g_bar_cnt = 0;
            __threadfence();
            g_bar_gen = gen + 1u;
        } else {
            while (g_bar_gen == gen) { }
        }
    }
    __syncthreads();
}

// =================================================================================
// Kernel 1: g_pre = x @ Vw^T + Vb + Wb   (unchanged from R2 — crossbar-balanced)
// =================================================================================
__global__ void __launch_bounds__(256) pre_gemm_kernel(
        const float* __restrict__ x,
        const float* __restrict__ Vw,
        const float* __restrict__ Wb,
        const float* __restrict__ Vb) {
    __shared__ float As[128][20];
    __shared__ float Ws[16][132];

    const int bm = blockIdx.x;
    const int bn = blockIdx.y;
    const int t  = threadIdx.x;
    const int tx = t & 15;
    const int ty = t >> 4;

    u64 acc[8][4];
    #pragma unroll
    for (int j = 0; j < 8; j++)
        #pragma unroll
        for (int p = 0; p < 4; p++) acc[j][p] = 0ull;

    const float* Arow = x  + (size_t)(bm*128) * II;
    const float* Wrow = Vw + (size_t)(bn*128) * II;

    for (int kb = 0; kb < II; kb += 16) {
        #pragma unroll
        for (int it = 0; it < 2; it++) {
            int q  = t + it*256;
            int r  = q >> 2;
            int k4 = (q & 3) << 2;
            float4 va = *(const float4*)(Arow + (size_t)r*II + kb + k4);
            *(float4*)&As[r][k4] = va;
            float4 vw = *(const float4*)(Wrow + (size_t)r*II + kb + k4);
            Ws[k4+0][r] = vw.x; Ws[k4+1][r] = vw.y;
            Ws[k4+2][r] = vw.z; Ws[k4+3][r] = vw.w;
        }
        __syncthreads();
        #pragma unroll
        for (int k = 0; k < 16; k++) {
            ulonglong2 w01 = *(const ulonglong2*)&Ws[k][tx*8];
            ulonglong2 w23 = *(const ulonglong2*)&Ws[k][tx*8 + 4];
            #pragma unroll
            for (int j = 0; j < 8; j++) {
                u64 ap = pack2s(As[ty*8 + j][k]);
                acc[j][0] = fma2(ap, w01.x, acc[j][0]);
                acc[j][1] = fma2(ap, w01.y, acc[j][1]);
                acc[j][2] = fma2(ap, w23.x, acc[j][2]);
                acc[j][3] = fma2(ap, w23.y, acc[j][3]);
            }
        }
        __syncthreads();
    }

    const int nbase = bn*128 + tx*8;
    float bias[8];
    #pragma unroll
    for (int i = 0; i < 8; i++) bias[i] = Vb[nbase+i] + Wb[nbase+i];

    #pragma unroll
    for (int j = 0; j < 8; j++) {
        size_t row = (size_t)bm*128 + ty*8 + j;
        float2 c0 = unpack2(acc[j][0]);
        float2 c1 = unpack2(acc[j][1]);
        float2 c2 = unpack2(acc[j][2]);
        float2 c3 = unpack2(acc[j][3]);
        float4 o0 = make_float4(c0.x+bias[0], c0.y+bias[1], c1.x+bias[2], c1.y+bias[3]);
        float4 o1 = make_float4(c2.x+bias[4], c2.y+bias[5], c3.x+bias[6], c3.y+bias[7]);
        *(float4*)&g_pre[row*HH + nbase]     = o0;
        *(float4*)&g_pre[row*HH + nbase + 4] = o1;
    }
}

// =================================================================================
// Kernel 2: persistent recurrence with point-to-point dataflow (no global barriers)
//   A-role: block (nt,kc), bid = kc*8+nt: partial[b 64][n 128] over k chunk 64,
//           Ww slice resident in SMEM as Ws[k][n].
//   B-role: block bid owns h columns [bid*8, bid*8+8): 64 rows x 8 cols = 512 =
//           256 threads x one float2. Reduce 16 partials + pre, tanh, write h_s.
//   Flags: aflag[blk]=s (partials of step s in buf s&1), bflag[blk]=s+1 (h_s done).
// =================================================================================
__global__ void __launch_bounds__(256) rnn_recurrent_kernel(
        const float* __restrict__ Ww,
        float* __restrict__ out) {
    extern __shared__ float smem[];
    float* Ws = smem;                 // [k=64][n=128] flat k*128+n : 32 KB
    float* As = smem + 64*128;        // [k=64][b pitch ASP]        : 17.4 KB

    const int bid = blockIdx.x;
    const int nt  = bid & (NT-1);     // 0..7
    const int kc  = bid >> 3;         // 0..15
    const int t   = threadIdx.x;
    const int tx  = t & 15;           // n group (8 cols)
    const int ty  = t >> 4;           // b group (4 rows)

    // ---- reset flags (visible after startup barrier) ----
    if (t == 0) { g_aflag[bid] = 0; g_bflag[bid] = 0; }

    // ---- load resident Ww slice transposed: Ws[k][n] = Ww[nt*128+n][kc*64+k] ----
    for (int q = t; q < 128*16; q += 256) {
        int n  = q >> 4;
        int k4 = (q & 15) << 2;
        float4 v = *(const float4*)(Ww + (size_t)(nt*128 + n)*HH + kc*64 + k4);
        Ws[(k4+0)*128 + n] = v.x;
        Ws[(k4+1)*128 + n] = v.y;
        Ws[(k4+2)*128 + n] = v.z;
        Ws[(k4+3)*128 + n] = v.w;
    }
    grid_sync_once();   // publishes flag resets; aligns wave start

    // ---- B-role: one float2 per thread (64 rows x 8 cols = 512 floats) ----
    const int rb = t & 63;                     // batch row 0..63
    const int rh = (t >> 6) << 1;              // 0,2,4,6 within 8 cols
    const size_t oOff = (size_t)rb*HH + bid*8 + rh;
    const int myNt = bid >> 4;                 // nt tile containing my 8 cols

    // ---- step 0: h_0 = tanh(pre_0) ----
    {
        float2 p = *(const float2*)&g_pre[oOff];
        float2 h = make_float2(tanh_fast(p.x), tanh_fast(p.y));
        *(float2*)&out[oOff] = h;
        __syncthreads();
        __threadfence();
        if (t == 0) flag_set(&g_bflag[bid], 1u);
    }

    float2 hlast = make_float2(0.f, 0.f);

    for (int s = 1; s < SS; s++) {
        // ---- A wait: h_{s-1} chunk ready (8 owners) + WAR on partial buf ----
        if (t < 8)        flag_wait_ge(&g_bflag[kc*8 + t], (unsigned)s);
        else if (t < 24)  flag_wait_ge(&g_bflag[nt*16 + (t-8)], (unsigned)(s-1));
        __syncthreads();

        // prefetch pre for B-role (independent of partials)
        float2 pre2 = *(const float2*)&g_pre[(size_t)s*BH + oOff];

        // ---- stage h_{s-1}[b][kc*64 ..] into As[k][b] (transposed) ----
        {
            const float* hbase = out + (size_t)(s-1)*BH;
            #pragma unroll
            for (int j = 0; j < 4; j++) {
                int b = t & 63;
                int k = (((t >> 6) + j*4) << 2);     // 0..60 step 4
                float4 v = __ldcg((const float4*)(hbase + (size_t)b*HH + kc*64 + k));
                As[(k+0)*ASP + b] = v.x;
                As[(k+1)*ASP + b] = v.y;
                As[(k+2)*ASP + b] = v.z;
                As[(k+3)*ASP + b] = v.w;
            }
        }
        __syncthreads();

        // ---- A compute: 4b x 8n per thread, FFMA2 ----
        u64 acc[4][4];
        #pragma unroll
        for (int j = 0; j < 4; j++)
            #pragma unroll
            for (int p = 0; p < 4; p++) acc[j][p] = 0ull;

        #pragma unroll 8
        for (int k = 0; k < 64; k++) {
            float4 a4 = *(const float4*)&As[k*ASP + ty*4];
            const float* wr = Ws + k*128 + tx*8;
            ulonglong2 w01 = *(const ulonglong2*)(wr);
            ulonglong2 w23 = *(const ulonglong2*)(wr + 4);
            u64 a0 = pack2s(a4.x);
            acc[0][0] = fma2(a0, w01.x, acc[0][0]);
            acc[0][1] = fma2(a0, w01.y, acc[0][1]);
            acc[0][2] = fma2(a0, w23.x, acc[0][2]);
            acc[0][3] = fma2(a0, w23.y, acc[0][3]);
            u64 a1 = pack2s(a4.y);
            acc[1][0] = fma2(a1, w01.x, acc[1][0]);
            acc[1][1] = fma2(a1, w01.y, acc[1][1]);
            acc[1][2] = fma2(a1, w23.x, acc[1][2]);
            acc[1][3] = fma2(a1, w23.y, acc[1][3]);
            u64 a2 = pack2s(a4.z);
            acc[2][0] = fma2(a2, w01.x, acc[2][0]);
            acc[2][1] = fma2(a2, w01.y, acc[2][1]);
            acc[2][2] = fma2(a2, w23.x, acc[2][2]);
            acc[2][3] = fma2(a2, w23.y, acc[2][3]);
            u64 a3 = pack2s(a4.w);
            acc[3][0] = fma2(a3, w01.x, acc[3][0]);
            acc[3][1] = fma2(a3, w01.y, acc[3][1]);
            acc[3][2] = fma2(a3, w23.x, acc[3][2]);
            acc[3][3] = fma2(a3, w23.y, acc[3][3]);
        }

        // ---- store partials to parity buffer ----
        {
            float* pb = &g_part2[s & 1][kc][0];
            #pragma unroll
            for (int j = 0; j < 4; j++) {
                float* dst = pb + (size_t)(ty*4 + j)*HH + nt*128 + tx*8;
                ulonglong2 v0; v0.x = acc[j][0]; v0.y = acc[j][1];
                ulonglong2 v1; v1.x = acc[j][2]; v1.y = acc[j][3];
                *(ulonglong2*)(dst)     = v0;
                *(ulonglong2*)(dst + 4) = v1;
            }
        }
        __syncthreads();
        __threadfence();
        if (t == 0) flag_set(&g_aflag[bid], (unsigned)s);

        // ---- B wait: all 16 k-chunk partials for my nt tile ----
        if (t < 16) flag_wait_ge(&g_aflag[t*8 + myNt], (unsigned)s);
        __syncthreads();

        // ---- B reduce + tanh + write h_s (one float2/thread) ----
        {
            float2 a2 = pre2;
            const float* pb = &g_part2[s & 1][0][0];
            #pragma unroll
            for (int kk = 0; kk < KC; kk++) {
                float2 p = __ldcg((const float2*)(pb + (size_t)kk*BH + oOff));
                a2.x += p.x; a2.y += p.y;
            }
            float2 h = make_float2(tanh_fast(a2.x), tanh_fast(a2.y));
            *(float2*)&out[(size_t)s*BH + oOff] = h;
            hlast = h;
        }
        __syncthreads();
        __threadfence();
        if (t == 0) flag_set(&g_bflag[bid], (unsigned)(s+1));
    }

    // h_final: values this thread computed at s=511
    *(float2*)&out[(size_t)SS*BH + oOff] = hlast;
}

// =================================================================================
// Launch
// =================================================================================
extern "C" void kernel_launch(void* const* d_in, const int* in_sizes, int n_in,
                              void* d_out, int out_size) {
    const float* x  = (const float*)d_in[0];   // (S,B,I)
    const float* Ww = (const float*)d_in[1];   // (H,H)
    const float* Wb = (const float*)d_in[2];   // (H)
    const float* Vw = (const float*)d_in[3];   // (H,I)
    const float* Vb = (const float*)d_in[4];   // (H)
    float* out = (float*)d_out;                // (S,B,H) then (1,B,H)

    dim3 g1(256, 8);
    pre_gemm_kernel<<<g1, 256>>>(x, Vw, Wb, Vb);

    static int smem_set = 0;
    const int smem_bytes = (64*128 + 64*ASP) * (int)sizeof(float);  // 50176
    if (!smem_set) {
        cudaFuncSetAttribute(rnn_recurrent_kernel,
                             cudaFuncAttributeMaxDynamicSharedMemorySize, smem_bytes);
        smem_set = 1;
    }
    rnn_recurrent_kernel<<<NB, 256, smem_bytes>>>(Ww, out);
}

// round 7
// speedup vs baseline: 1.5826x; 1.5826x over previous
#include <cuda_runtime.h>
#include <math.h>

// Problem dims
#define SS 512
#define BB 64
#define II 512
#define HH 1024
#define BH (BB*HH)

// Recurrent decomposition: 8 n-tiles (128 cols) x 16 k-chunks (64 k) = 128 blocks
#define NT 8
#define KC 16
#define NB (NT*KC)
#define ASP 68          // As row pitch (floats)

// -------------------- device scratch --------------------------------------------
__device__ float g_pre[SS*BH];            // V x_t + b_V + b_W
__device__ float g_part2[2][KC][BH];      // parity-buffered split-K partials (8 MB)
__device__ unsigned g_flag[NB*32];        // arrival slots, 128B stride
__device__ unsigned g_gen;                // broadcast release word

// -------------------- packed f32x2 helpers --------------------------------------
typedef unsigned long long u64;

__device__ __forceinline__ u64 pack2s(float x) {
    u64 r; asm("mov.b64 %0, {%1, %1};" : "=l"(r) : "f"(x)); return r;
}
__device__ __forceinline__ u64 fma2(u64 a, u64 b, u64 c) {
    u64 d; asm("fma.rn.f32x2 %0, %1, %2, %3;" : "=l"(d) : "l"(a), "l"(b), "l"(c));
    return d;
}
__device__ __forceinline__ float2 unpack2(u64 v) {
    float2 f; asm("mov.b64 {%0, %1}, %2;" : "=f"(f.x), "=f"(f.y) : "l"(v)); return f;
}
__device__ __forceinline__ float tanh_fast(float x) {
    float y; asm("tanh.approx.f32 %0, %1;" : "=f"(y) : "f"(x)); return y;
}

// =================================================================================
// Aggregator grid barrier.
//   Arrive:  t0 of each block: fence.gpu (cumulative) + relaxed store tag -> slot.
//   Detect:  block 0 threads 0..127 poll distinct slots (parallel lines).
//   Release: block 0 t0: fence + store tag -> g_gen; other blocks spin 1 thread.
// Tags are monotonic within a launch (1..1023); graph replays rewrite slots from
// tag 1 upward, and stale values (1023) never match an in-run tag before being
// overwritten, so no resets are needed.
// =================================================================================
__device__ __forceinline__ void bar_agg(int bid, int t, unsigned tag) {
    __syncthreads();
    if (t == 0) {
        __threadfence();   // cumulative release of this block's prior writes
        asm volatile("st.relaxed.gpu.global.b32 [%0], %1;"
                     :: "l"(&g_flag[bid*32]), "r"(tag) : "memory");
    }
    if (bid == 0) {
        if (t < NB) {
            unsigned v;
            const unsigned* p = &g_flag[t*32];
            do {
                asm volatile("ld.relaxed.gpu.global.b32 %0, [%1];"
                             : "=r"(v) : "l"(p) : "memory");
            } while (v != tag);
            __threadfence();   // cumulative acquire of observed releases
        }
        __syncthreads();
        if (t == 0) {
            asm volatile("st.relaxed.gpu.global.b32 [%0], %1;"
                         :: "l"(&g_gen), "r"(tag) : "memory");
        }
    } else {
        if (t == 0) {
            unsigned v;
            do {
                asm volatile("ld.relaxed.gpu.global.b32 %0, [%1];"
                             : "=r"(v) : "l"(&g_gen) : "memory");
            } while (v != tag);
            __threadfence();   // acquire: chain to block 0's fence
        }
    }
    __syncthreads();
}

// =================================================================================
// Kernel 1: g_pre = x @ Vw^T + Vb + Wb   (unchanged — crossbar-balanced FFMA2)
// =================================================================================
__global__ void __launch_bounds__(256) pre_gemm_kernel(
        const float* __restrict__ x,
        const float* __restrict__ Vw,
        const float* __restrict__ Wb,
        const float* __restrict__ Vb) {
    __shared__ float As[128][20];
    __shared__ float Ws[16][132];

    const int bm = blockIdx.x;
    const int bn = blockIdx.y;
    const int t  = threadIdx.x;
    const int tx = t & 15;
    const int ty = t >> 4;

    u64 acc[8][4];
    #pragma unroll
    for (int j = 0; j < 8; j++)
        #pragma unroll
        for (int p = 0; p < 4; p++) acc[j][p] = 0ull;

    const float* Arow = x  + (size_t)(bm*128) * II;
    const float* Wrow = Vw + (size_t)(bn*128) * II;

    for (int kb = 0; kb < II; kb += 16) {
        #pragma unroll
        for (int it = 0; it < 2; it++) {
            int q  = t + it*256;
            int r  = q >> 2;
            int k4 = (q & 3) << 2;
            float4 va = *(const float4*)(Arow + (size_t)r*II + kb + k4);
            *(float4*)&As[r][k4] = va;
            float4 vw = *(const float4*)(Wrow + (size_t)r*II + kb + k4);
            Ws[k4+0][r] = vw.x; Ws[k4+1][r] = vw.y;
            Ws[k4+2][r] = vw.z; Ws[k4+3][r] = vw.w;
        }
        __syncthreads();
        #pragma unroll
        for (int k = 0; k < 16; k++) {
            ulonglong2 w01 = *(const ulonglong2*)&Ws[k][tx*8];
            ulonglong2 w23 = *(const ulonglong2*)&Ws[k][tx*8 + 4];
            #pragma unroll
            for (int j = 0; j < 8; j++) {
                u64 ap = pack2s(As[ty*8 + j][k]);
                acc[j][0] = fma2(ap, w01.x, acc[j][0]);
                acc[j][1] = fma2(ap, w01.y, acc[j][1]);
                acc[j][2] = fma2(ap, w23.x, acc[j][2]);
                acc[j][3] = fma2(ap, w23.y, acc[j][3]);
            }
        }
        __syncthreads();
    }

    const int nbase = bn*128 + tx*8;
    float bias[8];
    #pragma unroll
    for (int i = 0; i < 8; i++) bias[i] = Vb[nbase+i] + Wb[nbase+i];

    #pragma unroll
    for (int j = 0; j < 8; j++) {
        size_t row = (size_t)bm*128 + ty*8 + j;
        float2 c0 = unpack2(acc[j][0]);
        float2 c1 = unpack2(acc[j][1]);
        float2 c2 = unpack2(acc[j][2]);
        float2 c3 = unpack2(acc[j][3]);
        float4 o0 = make_float4(c0.x+bias[0], c0.y+bias[1], c1.x+bias[2], c1.y+bias[3]);
        float4 o1 = make_float4(c2.x+bias[4], c2.y+bias[5], c3.x+bias[6], c3.y+bias[7]);
        *(float4*)&g_pre[row*HH + nbase]     = o0;
        *(float4*)&g_pre[row*HH + nbase + 4] = o1;
    }
}

// =================================================================================
// Kernel 2: persistent recurrence, R2 split-K structure + aggregator barriers.
//   A-role: block (nt,kc): partial[64b][128n] over k-chunk 64, Ww slice in SMEM.
//   B-role: block owns h cols [bid*8, +8): 256 thr x 1 float2 reduce+tanh.
// =================================================================================
__global__ void __launch_bounds__(256) rnn_recurrent_kernel(
        const float* __restrict__ Ww,
        float* __restrict__ out) {
    extern __shared__ float smem[];
    float* Ws = smem;                 // [k=64][n=128]  32 KB
    float* As = smem + 64*128;        // [k=64][b pitch ASP]

    const int bid = blockIdx.x;
    const int nt  = bid & (NT-1);
    const int kc  = bid >> 3;
    const int t   = threadIdx.x;
    const int tx  = t & 15;           // n group (8 cols)
    const int ty  = t >> 4;           // b group (4 rows)

    // Resident Ww slice transposed: Ws[k][n] = Ww[nt*128+n][kc*64+k]
    for (int q = t; q < 128*16; q += 256) {
        int n  = q >> 4;
        int k4 = (q & 15) << 2;
        float4 v = *(const float4*)(Ww + (size_t)(nt*128 + n)*HH + kc*64 + k4);
        Ws[(k4+0)*128 + n] = v.x;
        Ws[(k4+1)*128 + n] = v.y;
        Ws[(k4+2)*128 + n] = v.z;
        Ws[(k4+3)*128 + n] = v.w;
    }

    // B-role: one float2 per thread (64 rows x 8 cols = 512 floats)
    const int rb = t & 63;
    const int rh = (t >> 6) << 1;              // 0,2,4,6
    const size_t oOff = (size_t)rb*HH + bid*8 + rh;

    unsigned tag = 0;

    // step 0: h_0 = tanh(pre_0)
    {
        float2 p = *(const float2*)&g_pre[oOff];
        float2 h = make_float2(tanh_fast(p.x), tanh_fast(p.y));
        *(float2*)&out[oOff] = h;
    }
    tag++; bar_agg(bid, t, tag);

    float2 hlast = make_float2(0.f, 0.f);

    for (int s = 1; s < SS; s++) {
        // ---- stage h_{s-1}[b][kc*64..] into As[k][b] ----
        {
            const float* hbase = out + (size_t)(s-1)*BH;
            #pragma unroll
            for (int j = 0; j < 4; j++) {
                int b = t & 63;
                int k = (((t >> 6) + j*4) << 2);
                float4 v = __ldcg((const float4*)(hbase + (size_t)b*HH + kc*64 + k));
                As[(k+0)*ASP + b] = v.x;
                As[(k+1)*ASP + b] = v.y;
                As[(k+2)*ASP + b] = v.z;
                As[(k+3)*ASP + b] = v.w;
            }
        }
        __syncthreads();

        // ---- A compute: 4b x 8n per thread, FFMA2 ----
        u64 acc[4][4];
        #pragma unroll
        for (int j = 0; j < 4; j++)
            #pragma unroll
            for (int p = 0; p < 4; p++) acc[j][p] = 0ull;

        #pragma unroll 8
        for (int k = 0; k < 64; k++) {
            float4 a4 = *(const float4*)&As[k*ASP + ty*4];
            const float* wr = Ws + k*128 + tx*8;
            ulonglong2 w01 = *(const ulonglong2*)(wr);
            ulonglong2 w23 = *(const ulonglong2*)(wr + 4);
            u64 a0 = pack2s(a4.x);
            acc[0][0] = fma2(a0, w01.x, acc[0][0]);
            acc[0][1] = fma2(a0, w01.y, acc[0][1]);
            acc[0][2] = fma2(a0, w23.x, acc[0][2]);
            acc[0][3] = fma2(a0, w23.y, acc[0][3]);
            u64 a1 = pack2s(a4.y);
            acc[1][0] = fma2(a1, w01.x, acc[1][0]);
            acc[1][1] = fma2(a1, w01.y, acc[1][1]);
            acc[1][2] = fma2(a1, w23.x, acc[1][2]);
            acc[1][3] = fma2(a1, w23.y, acc[1][3]);
            u64 a2 = pack2s(a4.z);
            acc[2][0] = fma2(a2, w01.x, acc[2][0]);
            acc[2][1] = fma2(a2, w01.y, acc[2][1]);
            acc[2][2] = fma2(a2, w23.x, acc[2][2]);
            acc[2][3] = fma2(a2, w23.y, acc[2][3]);
            u64 a3 = pack2s(a4.w);
            acc[3][0] = fma2(a3, w01.x, acc[3][0]);
            acc[3][1] = fma2(a3, w01.y, acc[3][1]);
            acc[3][2] = fma2(a3, w23.x, acc[3][2]);
            acc[3][3] = fma2(a3, w23.y, acc[3][3]);
        }

        // ---- store partials to parity buffer ----
        {
            float* pb = &g_part2[s & 1][kc][0];
            #pragma unroll
            for (int j = 0; j < 4; j++) {
                float* dst = pb + (size_t)(ty*4 + j)*HH + nt*128 + tx*8;
                ulonglong2 v0; v0.x = acc[j][0]; v0.y = acc[j][1];
                ulonglong2 v1; v1.x = acc[j][2]; v1.y = acc[j][3];
                *(ulonglong2*)(dst)     = v0;
                *(ulonglong2*)(dst + 4) = v1;
            }
        }

        // prefetch pre for B-role (independent of partials)
        float2 pre2 = *(const float2*)&g_pre[(size_t)s*BH + oOff];

        tag++; bar_agg(bid, t, tag);      // all partials(s) visible

        // ---- B reduce + tanh + write h_s ----
        {
            float2 a2 = pre2;
            const float* pb = &g_part2[s & 1][0][0];
            #pragma unroll
            for (int kk = 0; kk < KC; kk++) {
                float2 p = __ldcg((const float2*)(pb + (size_t)kk*BH + oOff));
                a2.x += p.x; a2.y += p.y;
            }
            float2 h = make_float2(tanh_fast(a2.x), tanh_fast(a2.y));
            *(float2*)&out[(size_t)s*BH + oOff] = h;
            hlast = h;
        }

        tag++; bar_agg(bid, t, tag);      // all h_s visible
    }

    // h_final: values this thread computed at s=511
    *(float2*)&out[(size_t)SS*BH + oOff] = hlast;
}

// =================================================================================
// Launch
// =================================================================================
extern "C" void kernel_launch(void* const* d_in, const int* in_sizes, int n_in,
                              void* d_out, int out_size) {
    const float* x  = (const float*)d_in[0];   // (S,B,I)
    const float* Ww = (const float*)d_in[1];   // (H,H)
    const float* Wb = (const float*)d_in[2];   // (H)
    const float* Vw = (const float*)d_in[3];   // (H,I)
    const float* Vb = (const float*)d_in[4];   // (H)
    float* out = (float*)d_out;                // (S,B,H) then (1,B,H)

    dim3 g1(256, 8);
    pre_gemm_kernel<<<g1, 256>>>(x, Vw, Wb, Vb);

    static int smem_set = 0;
    const int smem_bytes = (64*128 + 64*ASP) * (int)sizeof(float);  // 50176
    if (!smem_set) {
        cudaFuncSetAttribute(rnn_recurrent_kernel,
                             cudaFuncAttributeMaxDynamicSharedMemorySize, smem_bytes);
        smem_set = 1;
    }
    rnn_recurrent_kernel<<<NB, 256, smem_bytes>>>(Ww, out);
}

// round 8
// speedup vs baseline: 1.8543x; 1.1717x over previous
#include <cuda_runtime.h>
#include <math.h>

// Problem dims
#define SS 512
#define BB 64
#define II 512
#define HH 1024
#define BH (BB*HH)

// Recurrent decomposition: 8 n-tiles (128 cols) x 16 k-chunks (64 k) = 128 blocks
#define NT 8
#define KC 16
#define NB (NT*KC)
#define ASP 68

// -------------------- device scratch --------------------------------------------
__device__ float g_pre[SS*BH];            // V x_t + b_V + b_W
__device__ float g_part2[2][KC][BH];      // parity-buffered split-K partials
// sync words, 128B-strided slots inside one array
//   [0,256)    prod_cnt[nt*32]      [256,512)  prod_gen[nt*32]
//   [512,768)  cons_cnt[nt*32]      [768,1024) cons_gen[nt*32]
//   [1024,1536) oct_cnt[kc*32]      [1536,2048) oct_gen[kc*32]
__device__ unsigned g_sync[2048];
__device__ unsigned g_bar_cnt = 0;
__device__ volatile unsigned g_bar_gen = 0;

#define PROD_CNT(nt) (&g_sync[(nt)*32])
#define PROD_GEN(nt) (&g_sync[256 + (nt)*32])
#define CONS_CNT(nt) (&g_sync[512 + (nt)*32])
#define CONS_GEN(nt) (&g_sync[768 + (nt)*32])
#define OCT_CNT(kc)  (&g_sync[1024 + (kc)*32])
#define OCT_GEN(kc)  (&g_sync[1536 + (kc)*32])

// -------------------- packed f32x2 helpers --------------------------------------
typedef unsigned long long u64;

__device__ __forceinline__ u64 pack2s(float x) {
    u64 r; asm("mov.b64 %0, {%1, %1};" : "=l"(r) : "f"(x)); return r;
}
__device__ __forceinline__ u64 fma2(u64 a, u64 b, u64 c) {
    u64 d; asm("fma.rn.f32x2 %0, %1, %2, %3;" : "=l"(d) : "l"(a), "l"(b), "l"(c));
    return d;
}
__device__ __forceinline__ float2 unpack2(u64 v) {
    float2 f; asm("mov.b64 {%0, %1}, %2;" : "=f"(f.x), "=f"(f.y) : "l"(v)); return f;
}
__device__ __forceinline__ float tanh_fast(float x) {
    float y; asm("tanh.approx.f32 %0, %1;" : "=f"(y) : "f"(x)); return y;
}
__device__ __forceinline__ void st_rlx(unsigned* p, unsigned v) {
    asm volatile("st.relaxed.gpu.global.b32 [%0], %1;" :: "l"(p), "r"(v) : "memory");
}
__device__ __forceinline__ unsigned ld_rlx(const unsigned* p) {
    unsigned v;
    asm volatile("ld.relaxed.gpu.global.b32 %0, [%1];" : "=r"(v) : "l"(p) : "memory");
    return v;
}
__device__ __forceinline__ void spin_ge(const unsigned* p, unsigned v) {
    while ((int)ld_rlx(p) < (int)v) { }
}

// startup global ticket barrier (R1/R2-proven; replay-safe: cnt self-resets,
// gen is monotonic and spin compares against the sampled value)
__device__ __forceinline__ void grid_sync_once() {
    __syncthreads();
    __threadfence();
    if (threadIdx.x == 0) {
        unsigned gen = g_bar_gen;
        if (atomicAdd(&g_bar_cnt, 1u) == NB - 1u) {
            g_bar_cnt = 0;
            __threadfence();
            g_bar_gen = gen + 1u;
        } else {
            while (g_bar_gen == gen) { }
        }
    }
    __syncthreads();
}

// =================================================================================
// Kernel 1: g_pre = x @ Vw^T + Vb + Wb  (bank-conflict-fixed w loads: tx*4 / +64)
// =================================================================================
__global__ void __launch_bounds__(256) pre_gemm_kernel(
        const float* __restrict__ x,
        const float* __restrict__ Vw,
        const float* __restrict__ Wb,
        const float* __restrict__ Vb) {
    __shared__ float As[128][20];
    __shared__ float Ws[16][132];

    const int bm = blockIdx.x;
    const int bn = blockIdx.y;
    const int t  = threadIdx.x;
    const int tx = t & 15;
    const int ty = t >> 4;

    u64 acc[8][4];
    #pragma unroll
    for (int j = 0; j < 8; j++)
        #pragma unroll
        for (int p = 0; p < 4; p++) acc[j][p] = 0ull;

    const float* Arow = x  + (size_t)(bm*128) * II;
    const float* Wrow = Vw + (size_t)(bn*128) * II;

    for (int kb = 0; kb < II; kb += 16) {
        #pragma unroll
        for (int it = 0; it < 2; it++) {
            int q  = t + it*256;
            int r  = q >> 2;
            int k4 = (q & 3) << 2;
            float4 va = *(const float4*)(Arow + (size_t)r*II + kb + k4);
            *(float4*)&As[r][k4] = va;
            float4 vw = *(const float4*)(Wrow + (size_t)r*II + kb + k4);
            Ws[k4+0][r] = vw.x; Ws[k4+1][r] = vw.y;
            Ws[k4+2][r] = vw.z; Ws[k4+3][r] = vw.w;
        }
        __syncthreads();
        #pragma unroll
        for (int k = 0; k < 16; k++) {
            ulonglong2 w01 = *(const ulonglong2*)&Ws[k][tx*4];        // cols tx*4..+3
            ulonglong2 w23 = *(const ulonglong2*)&Ws[k][tx*4 + 64];   // cols +64
            #pragma unroll
            for (int j = 0; j < 8; j++) {
                u64 ap = pack2s(As[ty*8 + j][k]);
                acc[j][0] = fma2(ap, w01.x, acc[j][0]);
                acc[j][1] = fma2(ap, w01.y, acc[j][1]);
                acc[j][2] = fma2(ap, w23.x, acc[j][2]);
                acc[j][3] = fma2(ap, w23.y, acc[j][3]);
            }
        }
        __syncthreads();
    }

    const int nb0 = bn*128 + tx*4;     // first 4 cols
    const int nb1 = nb0 + 64;          // second 4 cols
    float b0[4], b1[4];
    #pragma unroll
    for (int i = 0; i < 4; i++) {
        b0[i] = Vb[nb0+i] + Wb[nb0+i];
        b1[i] = Vb[nb1+i] + Wb[nb1+i];
    }

    #pragma unroll
    for (int j = 0; j < 8; j++) {
        size_t row = (size_t)bm*128 + ty*8 + j;
        float2 c0 = unpack2(acc[j][0]);
        float2 c1 = unpack2(acc[j][1]);
        float2 c2 = unpack2(acc[j][2]);
        float2 c3 = unpack2(acc[j][3]);
        float4 o0 = make_float4(c0.x+b0[0], c0.y+b0[1], c1.x+b0[2], c1.y+b0[3]);
        float4 o1 = make_float4(c2.x+b1[0], c2.y+b1[1], c3.x+b1[2], c3.y+b1[3]);
        *(float4*)&g_pre[row*HH + nb0] = o0;
        *(float4*)&g_pre[row*HH + nb1] = o1;
    }
}

// =================================================================================
// Kernel 2: persistent recurrence with GROUP-LOCAL ticket barriers.
//   A-role (nt,kc): partial[64b][128n] over k-chunk 64. Arrive PROD(nt), 16 arr.
//   B-role bid: h cols [bid*8,+8) = inside n-tile myNt=bid>>4 AND inside its own
//   octet's k-chunk (bid*8 = kc*64 + nt*8). Wait PROD_GEN(myNt) >= s.
//   Octet barrier OCT(kc): 8 blocks [kc*8,+8) write/consume the same h chunk.
//   WAR: CONS(nt) with 2-step slack guards parity partial buffers.
// =================================================================================
__global__ void __launch_bounds__(256) rnn_recurrent_kernel(
        const float* __restrict__ Ww,
        float* __restrict__ out) {
    extern __shared__ float smem[];
    float* Ws = smem;                 // [k=64][n=128]  32 KB
    float* As = smem + 64*128;        // [k=64][b pitch ASP]

    const int bid = blockIdx.x;
    const int nt  = bid & (NT-1);
    const int kc  = bid >> 3;
    const int t   = threadIdx.x;
    const int tx  = t & 15;           // n group
    const int ty  = t >> 4;           // b group (4 rows)
    const int myNt = bid >> 4;        // n-tile containing my B-cols

    // zero sync words before startup barrier (block 0 only)
    if (bid == 0) {
        for (int i = t; i < 2048; i += 256) g_sync[i] = 0;
    }

    // Resident Ww slice transposed: Ws[k][n] = Ww[nt*128+n][kc*64+k]
    for (int q = t; q < 128*16; q += 256) {
        int n  = q >> 4;
        int k4 = (q & 15) << 2;
        float4 v = *(const float4*)(Ww + (size_t)(nt*128 + n)*HH + kc*64 + k4);
        Ws[(k4+0)*128 + n] = v.x;
        Ws[(k4+1)*128 + n] = v.y;
        Ws[(k4+2)*128 + n] = v.z;
        Ws[(k4+3)*128 + n] = v.w;
    }
    grid_sync_once();    // publishes zeroed sync words to all blocks

    // B-role: one float2 per thread (64 rows x 8 cols)
    const int rb = t & 63;
    const int rh = (t >> 6) << 1;     // 0,2,4,6
    const size_t oOff = (size_t)rb*HH + bid*8 + rh;

    // ---- step 0: h_0 = tanh(pre_0) ----
    {
        float2 p = *(const float2*)&g_pre[oOff];
        float2 h = make_float2(tanh_fast(p.x), tanh_fast(p.y));
        *(float2*)&out[oOff] = h;
    }
    // octet barrier, tag 1
    __syncthreads();
    if (t == 0) {
        __threadfence();
        if (atomicAdd(OCT_CNT(kc), 1u) == 8u*1u - 1u) {
            __threadfence();
            st_rlx(OCT_GEN(kc), 1u);
        }
        spin_ge(OCT_GEN(kc), 1u);
        __threadfence();
    }
    __syncthreads();

    float2 hlast = make_float2(0.f, 0.f);

    for (int s = 1; s < SS; s++) {
        // WAR guard on parity buffer (2-step slack; almost never blocks)
        if (s >= 3 && t == 0) spin_ge(CONS_GEN(nt), (unsigned)(s-2));

        // ---- stage h_{s-1}[b][kc*64..] into As[k][b] ----
        {
            const float* hbase = out + (size_t)(s-1)*BH;
            #pragma unroll
            for (int j = 0; j < 4; j++) {
                int b = t & 63;
                int k = (((t >> 6) + j*4) << 2);
                float4 v = __ldcg((const float4*)(hbase + (size_t)b*HH + kc*64 + k));
                As[(k+0)*ASP + b] = v.x;
                As[(k+1)*ASP + b] = v.y;
                As[(k+2)*ASP + b] = v.z;
                As[(k+3)*ASP + b] = v.w;
            }
        }
        __syncthreads();   // also joins the t0 WAR spin

        // ---- A compute: 4b x 8n (cols tx*4..+3 and 64+tx*4..+3), FFMA2 ----
        u64 acc[4][4];
        #pragma unroll
        for (int j = 0; j < 4; j++)
            #pragma unroll
            for (int p = 0; p < 4; p++) acc[j][p] = 0ull;

        #pragma unroll 8
        for (int k = 0; k < 64; k++) {
            float4 a4 = *(const float4*)&As[k*ASP + ty*4];
            const float* wr = Ws + k*128 + tx*4;
            ulonglong2 w01 = *(const ulonglong2*)(wr);        // conflict-free
            ulonglong2 w23 = *(const ulonglong2*)(wr + 64);
            u64 a0 = pack2s(a4.x);
            acc[0][0] = fma2(a0, w01.x, acc[0][0]);
            acc[0][1] = fma2(a0, w01.y, acc[0][1]);
            acc[0][2] = fma2(a0, w23.x, acc[0][2]);
            acc[0][3] = fma2(a0, w23.y, acc[0][3]);
            u64 a1 = pack2s(a4.y);
            acc[1][0] = fma2(a1, w01.x, acc[1][0]);
            acc[1][1] = fma2(a1, w01.y, acc[1][1]);
            acc[1][2] = fma2(a1, w23.x, acc[1][2]);
            acc[1][3] = fma2(a1, w23.y, acc[1][3]);
            u64 a2 = pack2s(a4.z);
            acc[2][0] = fma2(a2, w01.x, acc[2][0]);
            acc[2][1] = fma2(a2, w01.y, acc[2][1]);
            acc[2][2] = fma2(a2, w23.x, acc[2][2]);
            acc[2][3] = fma2(a2, w23.y, acc[2][3]);
            u64 a3 = pack2s(a4.w);
            acc[3][0] = fma2(a3, w01.x, acc[3][0]);
            acc[3][1] = fma2(a3, w01.y, acc[3][1]);
            acc[3][2] = fma2(a3, w23.x, acc[3][2]);
            acc[3][3] = fma2(a3, w23.y, acc[3][3]);
        }

        // ---- store partials (parity buffer) ----
        {
            float* pb = &g_part2[s & 1][kc][0];
            #pragma unroll
            for (int j = 0; j < 4; j++) {
                float* dst = pb + (size_t)(ty*4 + j)*HH + nt*128 + tx*4;
                ulonglong2 v0; v0.x = acc[j][0]; v0.y = acc[j][1];
                ulonglong2 v1; v1.x = acc[j][2]; v1.y = acc[j][3];
                *(ulonglong2*)(dst)      = v0;
                *(ulonglong2*)(dst + 64) = v1;
            }
        }

        // prefetch pre for B-role
        float2 pre2 = *(const float2*)&g_pre[(size_t)s*BH + oOff];

        // ---- producer barrier for n-tile nt (16 arrivals); wait on myNt ----
        __syncthreads();
        if (t == 0) {
            __threadfence();
            if (atomicAdd(PROD_CNT(nt), 1u) == (unsigned)(s*16 - 1)) {
                __threadfence();
                st_rlx(PROD_GEN(nt), (unsigned)s);
            }
            spin_ge(PROD_GEN(myNt), (unsigned)s);
            __threadfence();
        }
        __syncthreads();

        // ---- B reduce + tanh + write h_s ----
        {
            float2 a2 = pre2;
            const float* pb = &g_part2[s & 1][0][0];
            #pragma unroll
            for (int kk = 0; kk < KC; kk++) {
                float2 p = __ldcg((const float2*)(pb + (size_t)kk*BH + oOff));
                a2.x += p.x; a2.y += p.y;
            }
            float2 h = make_float2(tanh_fast(a2.x), tanh_fast(a2.y));
            *(float2*)&out[(size_t)s*BH + oOff] = h;
            hlast = h;
        }

        // ---- consumer arrive (WAR release) + octet barrier (h chunk ready) ----
        __syncthreads();
        if (t == 0) {
            __threadfence();
            if (atomicAdd(CONS_CNT(myNt), 1u) == (unsigned)(s*16 - 1))
                st_rlx(CONS_GEN(myNt), (unsigned)s);
            if (atomicAdd(OCT_CNT(kc), 1u) == (unsigned)((s+1)*8 - 1)) {
                __threadfence();
                st_rlx(OCT_GEN(kc), (unsigned)(s+1));
            }
            spin_ge(OCT_GEN(kc), (unsigned)(s+1));
            __threadfence();
        }
        __syncthreads();
    }

    // h_final: values this thread computed at s=511
    *(float2*)&out[(size_t)SS*BH + oOff] = hlast;
}

// =================================================================================
// Launch
// =================================================================================
extern "C" void kernel_launch(void* const* d_in, const int* in_sizes, int n_in,
                              void* d_out, int out_size) {
    const float* x  = (const float*)d_in[0];   // (S,B,I)
    const float* Ww = (const float*)d_in[1];   // (H,H)
    const float* Wb = (const float*)d_in[2];   // (H)
    const float* Vw = (const float*)d_in[3];   // (H,I)
    const float* Vb = (const float*)d_in[4];   // (H)
    float* out = (float*)d_out;                // (S,B,H) then (1,B,H)

    dim3 g1(256, 8);
    pre_gemm_kernel<<<g1, 256>>>(x, Vw, Wb, Vb);

    static int smem_set = 0;
    const int smem_bytes = (64*128 + 64*ASP) * (int)sizeof(float);  // 50176
    if (!smem_set) {
        cudaFuncSetAttribute(rnn_recurrent_kernel,
                             cudaFuncAttributeMaxDynamicSharedMemorySize, smem_bytes);
        smem_set = 1;
    }
    rnn_recurrent_kernel<<<NB, 256, smem_bytes>>>(Ww, out);
}

// round 9
// speedup vs baseline: 2.0229x; 1.0909x over previous
#include <cuda_runtime.h>
#include <math.h>

// Problem dims
#define SS 512
#define BB 64
#define II 512
#define HH 1024
#define BH (BB*HH)

// Recurrent decomposition: 8 n-tiles (128 cols) x 16 k-chunks (64 k) = 128 blocks
#define NT 8
#define KC 16
#define NB (NT*KC)
#define ASP 68          // As row pitch (floats)

// -------------------- device scratch --------------------------------------------
__device__ float g_pre[SS*BH];        // V x_t + b_V + b_W
__device__ float g_part[KC][BH];      // split-K partials (single buffer, R2-style)
__device__ unsigned g_bar_cnt = 0;
__device__ volatile unsigned g_bar_gen = 0;

// -------------------- packed f32x2 helpers --------------------------------------
typedef unsigned long long u64;

__device__ __forceinline__ u64 pack2s(float x) {
    u64 r; asm("mov.b64 %0, {%1, %1};" : "=l"(r) : "f"(x)); return r;
}
__device__ __forceinline__ u64 fma2(u64 a, u64 b, u64 c) {
    u64 d; asm("fma.rn.f32x2 %0, %1, %2, %3;" : "=l"(d) : "l"(a), "l"(b), "l"(c));
    return d;
}
__device__ __forceinline__ float2 unpack2(u64 v) {
    float2 f; asm("mov.b64 {%0, %1}, %2;" : "=f"(f.x), "=f"(f.y) : "l"(v)); return f;
}
__device__ __forceinline__ float tanh_fast(float x) {
    float y; asm("tanh.approx.f32 %0, %1;" : "=f"(y) : "f"(x)); return y;
}

// -------------------- global ticket barrier (R2-proven best) ---------------------
__device__ __forceinline__ void grid_sync() {
    __syncthreads();
    __threadfence();
    if (threadIdx.x == 0) {
        unsigned gen = g_bar_gen;
        if (atomicAdd(&g_bar_cnt, 1u) == NB - 1u) {
            g_bar_cnt = 0;
            __threadfence();
            g_bar_gen = gen + 1u;
        } else {
            while (g_bar_gen == gen) { }
        }
    }
    __syncthreads();
}

// =================================================================================
// Kernel 1: g_pre = x @ Vw^T + Vb + Wb  (conflict-free w loads: tx*4 / +64)
// =================================================================================
__global__ void __launch_bounds__(256) pre_gemm_kernel(
        const float* __restrict__ x,
        const float* __restrict__ Vw,
        const float* __restrict__ Wb,
        const float* __restrict__ Vb) {
    __shared__ float As[128][20];
    __shared__ float Ws[16][132];

    const int bm = blockIdx.x;
    const int bn = blockIdx.y;
    const int t  = threadIdx.x;
    const int tx = t & 15;
    const int ty = t >> 4;

    u64 acc[8][4];
    #pragma unroll
    for (int j = 0; j < 8; j++)
        #pragma unroll
        for (int p = 0; p < 4; p++) acc[j][p] = 0ull;

    const float* Arow = x  + (size_t)(bm*128) * II;
    const float* Wrow = Vw + (size_t)(bn*128) * II;

    for (int kb = 0; kb < II; kb += 16) {
        #pragma unroll
        for (int it = 0; it < 2; it++) {
            int q  = t + it*256;
            int r  = q >> 2;
            int k4 = (q & 3) << 2;
            float4 va = *(const float4*)(Arow + (size_t)r*II + kb + k4);
            *(float4*)&As[r][k4] = va;
            float4 vw = *(const float4*)(Wrow + (size_t)r*II + kb + k4);
            Ws[k4+0][r] = vw.x; Ws[k4+1][r] = vw.y;
            Ws[k4+2][r] = vw.z; Ws[k4+3][r] = vw.w;
        }
        __syncthreads();
        #pragma unroll
        for (int k = 0; k < 16; k++) {
            ulonglong2 w01 = *(const ulonglong2*)&Ws[k][tx*4];        // cols tx*4..+3
            ulonglong2 w23 = *(const ulonglong2*)&Ws[k][tx*4 + 64];   // cols +64
            #pragma unroll
            for (int j = 0; j < 8; j++) {
                u64 ap = pack2s(As[ty*8 + j][k]);
                acc[j][0] = fma2(ap, w01.x, acc[j][0]);
                acc[j][1] = fma2(ap, w01.y, acc[j][1]);
                acc[j][2] = fma2(ap, w23.x, acc[j][2]);
                acc[j][3] = fma2(ap, w23.y, acc[j][3]);
            }
        }
        __syncthreads();
    }

    const int nb0 = bn*128 + tx*4;
    const int nb1 = nb0 + 64;
    float b0[4], b1[4];
    #pragma unroll
    for (int i = 0; i < 4; i++) {
        b0[i] = Vb[nb0+i] + Wb[nb0+i];
        b1[i] = Vb[nb1+i] + Wb[nb1+i];
    }

    #pragma unroll
    for (int j = 0; j < 8; j++) {
        size_t row = (size_t)bm*128 + ty*8 + j;
        float2 c0 = unpack2(acc[j][0]);
        float2 c1 = unpack2(acc[j][1]);
        float2 c2 = unpack2(acc[j][2]);
        float2 c3 = unpack2(acc[j][3]);
        float4 o0 = make_float4(c0.x+b0[0], c0.y+b0[1], c1.x+b0[2], c1.y+b0[3]);
        float4 o1 = make_float4(c2.x+b1[0], c2.y+b1[1], c3.x+b1[2], c3.y+b1[3]);
        *(float4*)&g_pre[row*HH + nb0] = o0;
        *(float4*)&g_pre[row*HH + nb1] = o1;
    }
}

// =================================================================================
// Kernel 2: persistent recurrence — R2 structure (two global tickets/step,
// single partial buffer) + conflict-free w microkernel + transposed staging.
//   A-role (nt,kc): partial[64b][128n] over k-chunk 64, Ww slice in SMEM [k][n].
//   B-role bid: h cols [bid*8,+8), 256 thr x 1 float2 reduce + tanh.
// =================================================================================
__global__ void __launch_bounds__(256) rnn_recurrent_kernel(
        const float* __restrict__ Ww,
        float* __restrict__ out) {
    extern __shared__ float smem[];
    float* Ws = smem;                 // [k=64][n=128]  32 KB
    float* As = smem + 64*128;        // [k=64][b pitch ASP]

    const int bid = blockIdx.x;
    const int nt  = bid & (NT-1);
    const int kc  = bid >> 3;
    const int t   = threadIdx.x;
    const int tx  = t & 15;           // n group
    const int ty  = t >> 4;           // b group (4 rows)

    // Resident Ww slice transposed: Ws[k][n] = Ww[nt*128+n][kc*64+k]
    for (int q = t; q < 128*16; q += 256) {
        int n  = q >> 4;
        int k4 = (q & 15) << 2;
        float4 v = *(const float4*)(Ww + (size_t)(nt*128 + n)*HH + kc*64 + k4);
        Ws[(k4+0)*128 + n] = v.x;
        Ws[(k4+1)*128 + n] = v.y;
        Ws[(k4+2)*128 + n] = v.z;
        Ws[(k4+3)*128 + n] = v.w;
    }

    // B-role: one float2 per thread (64 rows x 8 cols = 512 floats)
    const int rb = t & 63;
    const int rh = (t >> 6) << 1;     // 0,2,4,6
    const size_t oOff = (size_t)rb*HH + bid*8 + rh;

    // ---- step 0: h_0 = tanh(pre_0) ----
    {
        float2 p = *(const float2*)&g_pre[oOff];
        float2 h = make_float2(tanh_fast(p.x), tanh_fast(p.y));
        *(float2*)&out[oOff] = h;
    }
    grid_sync();

    float2 hlast = make_float2(0.f, 0.f);

    for (int s = 1; s < SS; s++) {
        // ---- stage h_{s-1}[b][kc*64..] into As[k][b] (transposed) ----
        {
            const float* hbase = out + (size_t)(s-1)*BH;
            #pragma unroll
            for (int j = 0; j < 4; j++) {
                int b = t & 63;
                int k = (((t >> 6) + j*4) << 2);
                float4 v = __ldcg((const float4*)(hbase + (size_t)b*HH + kc*64 + k));
                As[(k+0)*ASP + b] = v.x;
                As[(k+1)*ASP + b] = v.y;
                As[(k+2)*ASP + b] = v.z;
                As[(k+3)*ASP + b] = v.w;
            }
        }
        __syncthreads();

        // ---- A compute: 4b x 8n per thread (cols tx*4..+3 and 64+tx*4..+3) ----
        u64 acc[4][4];
        #pragma unroll
        for (int j = 0; j < 4; j++)
            #pragma unroll
            for (int p = 0; p < 4; p++) acc[j][p] = 0ull;

        #pragma unroll 8
        for (int k = 0; k < 64; k++) {
            float4 a4 = *(const float4*)&As[k*ASP + ty*4];
            const float* wr = Ws + k*128 + tx*4;
            ulonglong2 w01 = *(const ulonglong2*)(wr);        // conflict-free 16B stride
            ulonglong2 w23 = *(const ulonglong2*)(wr + 64);
            u64 a0 = pack2s(a4.x);
            acc[0][0] = fma2(a0, w01.x, acc[0][0]);
            acc[0][1] = fma2(a0, w01.y, acc[0][1]);
            acc[0][2] = fma2(a0, w23.x, acc[0][2]);
            acc[0][3] = fma2(a0, w23.y, acc[0][3]);
            u64 a1 = pack2s(a4.y);
            acc[1][0] = fma2(a1, w01.x, acc[1][0]);
            acc[1][1] = fma2(a1, w01.y, acc[1][1]);
            acc[1][2] = fma2(a1, w23.x, acc[1][2]);
            acc[1][3] = fma2(a1, w23.y, acc[1][3]);
            u64 a2 = pack2s(a4.z);
            acc[2][0] = fma2(a2, w01.x, acc[2][0]);
            acc[2][1] = fma2(a2, w01.y, acc[2][1]);
            acc[2][2] = fma2(a2, w23.x, acc[2][2]);
            acc[2][3] = fma2(a2, w23.y, acc[2][3]);
            u64 a3 = pack2s(a4.w);
            acc[3][0] = fma2(a3, w01.x, acc[3][0]);
            acc[3][1] = fma2(a3, w01.y, acc[3][1]);
            acc[3][2] = fma2(a3, w23.x, acc[3][2]);
            acc[3][3] = fma2(a3, w23.y, acc[3][3]);
        }

        // ---- store partials (cols tx*4 and 64+tx*4) ----
        #pragma unroll
        for (int j = 0; j < 4; j++) {
            float* dst = &g_part[kc][(size_t)(ty*4 + j)*HH + nt*128 + tx*4];
            ulonglong2 v0; v0.x = acc[j][0]; v0.y = acc[j][1];
            ulonglong2 v1; v1.x = acc[j][2]; v1.y = acc[j][3];
            *(ulonglong2*)(dst)      = v0;
            *(ulonglong2*)(dst + 64) = v1;
        }

        // prefetch pre for B-role (independent of partials)
        float2 pre2 = *(const float2*)&g_pre[(size_t)s*BH + oOff];

        grid_sync();    // all partials(s) visible

        // ---- B reduce + tanh + write h_s ----
        {
            float2 a2 = pre2;
            #pragma unroll
            for (int kk = 0; kk < KC; kk++) {
                float2 p = __ldcg((const float2*)&g_part[kk][oOff]);
                a2.x += p.x; a2.y += p.y;
            }
            float2 h = make_float2(tanh_fast(a2.x), tanh_fast(a2.y));
            *(float2*)&out[(size_t)s*BH + oOff] = h;
            hlast = h;
        }

        grid_sync();    // all h_s visible; also guards partial-buffer WAR
    }

    // h_final: values this thread computed at s=511
    *(float2*)&out[(size_t)SS*BH + oOff] = hlast;
}

// =================================================================================
// Launch
// =================================================================================
extern "C" void kernel_launch(void* const* d_in, const int* in_sizes, int n_in,
                              void* d_out, int out_size) {
    const float* x  = (const float*)d_in[0];   // (S,B,I)
    const float* Ww = (const float*)d_in[1];   // (H,H)
    const float* Wb = (const float*)d_in[2];   // (H)
    const float* Vw = (const float*)d_in[3];   // (H,I)
    const float* Vb = (const float*)d_in[4];   // (H)
    float* out = (float*)d_out;                // (S,B,H) then (1,B,H)

    dim3 g1(256, 8);
    pre_gemm_kernel<<<g1, 256>>>(x, Vw, Wb, Vb);

    static int smem_set = 0;
    const int smem_bytes = (64*128 + 64*ASP) * (int)sizeof(float);  // 50176
    if (!smem_set) {
        cudaFuncSetAttribute(rnn_recurrent_kernel,
                             cudaFuncAttributeMaxDynamicSharedMemorySize, smem_bytes);
        smem_set = 1;
    }
    rnn_recurrent_kernel<<<NB, 256, smem_bytes>>>(Ww, out);
}

// round 10
// speedup vs baseline: 2.3367x; 1.1551x over previous
#include <cuda_runtime.h>
#include <math.h>

// Problem dims
#define SS 512
#define BB 64
#define II 512
#define HH 1024
#define BH (BB*HH)

// Recurrent decomposition: 8 n-tiles (128 cols) x 16 k-chunks (64 k) = 128 blocks
#define NT 8
#define KC 16
#define NB (NT*KC)
#define ASP 68          // As row pitch in floats ([k][b] layout, 64 b + pad)

// -------------------- device scratch --------------------------------------------
__device__ float g_pre[SS*BH];        // V x_t + b_V + b_W
__device__ float g_part[KC][BH];      // split-K partials (single buffer)
__device__ float g_hT[2][HH*BB];      // parity-buffered TRANSPOSED h: hT[c][b]
__device__ unsigned g_bar_cnt = 0;
__device__ volatile unsigned g_bar_gen = 0;

// -------------------- packed f32x2 helpers --------------------------------------
typedef unsigned long long u64;

__device__ __forceinline__ u64 pack2s(float x) {
    u64 r; asm("mov.b64 %0, {%1, %1};" : "=l"(r) : "f"(x)); return r;
}
__device__ __forceinline__ u64 fma2(u64 a, u64 b, u64 c) {
    u64 d; asm("fma.rn.f32x2 %0, %1, %2, %3;" : "=l"(d) : "l"(a), "l"(b), "l"(c));
    return d;
}
__device__ __forceinline__ float2 unpack2(u64 v) {
    float2 f; asm("mov.b64 {%0, %1}, %2;" : "=f"(f.x), "=f"(f.y) : "l"(v)); return f;
}
__device__ __forceinline__ float tanh_fast(float x) {
    float y; asm("tanh.approx.f32 %0, %1;" : "=f"(y) : "f"(x)); return y;
}

// -------------------- global ticket barrier (R2-proven best) ---------------------
__device__ __forceinline__ void grid_sync() {
    __syncthreads();
    __threadfence();
    if (threadIdx.x == 0) {
        unsigned gen = g_bar_gen;
        if (atomicAdd(&g_bar_cnt, 1u) == NB - 1u) {
            g_bar_cnt = 0;
            __threadfence();
            g_bar_gen = gen + 1u;
        } else {
            while (g_bar_gen == gen) { }
        }
    }
    __syncthreads();
}

// =================================================================================
// Kernel 1: g_pre = x @ Vw^T + Vb + Wb  (R9 conflict-free version, proven)
// =================================================================================
__global__ void __launch_bounds__(256) pre_gemm_kernel(
        const float* __restrict__ x,
        const float* __restrict__ Vw,
        const float* __restrict__ Wb,
        const float* __restrict__ Vb) {
    __shared__ float As[128][20];
    __shared__ float Ws[16][132];

    const int bm = blockIdx.x;
    const int bn = blockIdx.y;
    const int t  = threadIdx.x;
    const int tx = t & 15;
    const int ty = t >> 4;

    u64 acc[8][4];
    #pragma unroll
    for (int j = 0; j < 8; j++)
        #pragma unroll
        for (int p = 0; p < 4; p++) acc[j][p] = 0ull;

    const float* Arow = x  + (size_t)(bm*128) * II;
    const float* Wrow = Vw + (size_t)(bn*128) * II;

    for (int kb = 0; kb < II; kb += 16) {
        #pragma unroll
        for (int it = 0; it < 2; it++) {
            int q  = t + it*256;
            int r  = q >> 2;
            int k4 = (q & 3) << 2;
            float4 va = *(const float4*)(Arow + (size_t)r*II + kb + k4);
            *(float4*)&As[r][k4] = va;
            float4 vw = *(const float4*)(Wrow + (size_t)r*II + kb + k4);
            Ws[k4+0][r] = vw.x; Ws[k4+1][r] = vw.y;
            Ws[k4+2][r] = vw.z; Ws[k4+3][r] = vw.w;
        }
        __syncthreads();
        #pragma unroll
        for (int k = 0; k < 16; k++) {
            ulonglong2 w01 = *(const ulonglong2*)&Ws[k][tx*4];
            ulonglong2 w23 = *(const ulonglong2*)&Ws[k][tx*4 + 64];
            #pragma unroll
            for (int j = 0; j < 8; j++) {
                u64 ap = pack2s(As[ty*8 + j][k]);
                acc[j][0] = fma2(ap, w01.x, acc[j][0]);
                acc[j][1] = fma2(ap, w01.y, acc[j][1]);
                acc[j][2] = fma2(ap, w23.x, acc[j][2]);
                acc[j][3] = fma2(ap, w23.y, acc[j][3]);
            }
        }
        __syncthreads();
    }

    const int nb0 = bn*128 + tx*4;
    const int nb1 = nb0 + 64;
    float b0[4], b1[4];
    #pragma unroll
    for (int i = 0; i < 4; i++) {
        b0[i] = Vb[nb0+i] + Wb[nb0+i];
        b1[i] = Vb[nb1+i] + Wb[nb1+i];
    }

    #pragma unroll
    for (int j = 0; j < 8; j++) {
        size_t row = (size_t)bm*128 + ty*8 + j;
        float2 c0 = unpack2(acc[j][0]);
        float2 c1 = unpack2(acc[j][1]);
        float2 c2 = unpack2(acc[j][2]);
        float2 c3 = unpack2(acc[j][3]);
        float4 o0 = make_float4(c0.x+b0[0], c0.y+b0[1], c1.x+b0[2], c1.y+b0[3]);
        float4 o1 = make_float4(c2.x+b1[0], c2.y+b1[1], c3.x+b1[2], c3.y+b1[3]);
        *(float4*)&g_pre[row*HH + nb0] = o0;
        *(float4*)&g_pre[row*HH + nb1] = o1;
    }
}

// =================================================================================
// Kernel 2: persistent recurrence.
//   128 threads, 8b x 8n micro (crossbar-optimal), conflict-free w loads,
//   transposed h exchange (g_hT[c][b], parity-buffered) for coalesced staging.
//   A-role (nt,kc): partial[64b][128n] over k-chunk 64; Ww slice in SMEM [k][n].
//   B-role: linear float4 slice o = (bid*128+t)*4; reduce 16 partials + tanh,
//           write out (coalesced) + hT (scattered, fire-and-forget).
// =================================================================================
__global__ void __launch_bounds__(128) rnn_recurrent_kernel(
        const float* __restrict__ Ww,
        float* __restrict__ out) {
    extern __shared__ float smem[];
    float* Ws = smem;                 // [k=64][n=128]  32 KB
    float* As = smem + 64*128;        // [k=64][b pitch ASP] 17.4 KB

    const int bid = blockIdx.x;
    const int nt  = bid & (NT-1);
    const int kc  = bid >> 3;
    const int t   = threadIdx.x;
    const int tx  = t & 15;           // n group (8 cols as tx*4 and 64+tx*4)
    const int ty  = t >> 4;           // b group (8 rows)

    // Resident Ww slice transposed: Ws[k][n] = Ww[nt*128+n][kc*64+k]
    for (int q = t; q < 128*16; q += 128) {
        int n  = q >> 4;
        int k4 = (q & 15) << 2;
        float4 v = *(const float4*)(Ww + (size_t)(nt*128 + n)*HH + kc*64 + k4);
        Ws[(k4+0)*128 + n] = v.x;
        Ws[(k4+1)*128 + n] = v.y;
        Ws[(k4+2)*128 + n] = v.z;
        Ws[(k4+3)*128 + n] = v.w;
    }

    // B-role: linear float4 slice (128 blk * 128 thr * 4 = BH)
    const int o   = (bid*128 + t)*4;
    const int ob  = o >> 10;          // batch row
    const int oc  = o & 1023;         // first of 4 consecutive cols

    // ---- step 0: h_0 = tanh(pre_0) ----
    {
        float4 p = *(const float4*)&g_pre[o];
        float4 h = make_float4(tanh_fast(p.x), tanh_fast(p.y),
                               tanh_fast(p.z), tanh_fast(p.w));
        *(float4*)&out[o] = h;
        float* hT = &g_hT[0][0];
        hT[(oc+0)*BB + ob] = h.x;
        hT[(oc+1)*BB + ob] = h.y;
        hT[(oc+2)*BB + ob] = h.z;
        hT[(oc+3)*BB + ob] = h.w;
    }
    grid_sync();

    float4 hlast = make_float4(0.f, 0.f, 0.f, 0.f);

    for (int s = 1; s < SS; s++) {
        // ---- stage hT chunk [kc*64 .. +64)[b] : fully contiguous 16KB ----
        {
            const float* src = &g_hT[(s-1) & 1][kc*64*BB];
            float* dstBase = As;
            #pragma unroll
            for (int j = 0; j < 8; j++) {
                int off4 = t + j*128;          // float4 index, 0..1023
                int kk   = off4 >> 4;          // k row (16 float4 per row)
                int b4   = (off4 & 15) << 2;   // b offset
                float4 v = __ldcg((const float4*)(src + off4*4));
                *(float4*)&dstBase[kk*ASP + b4] = v;
            }
        }
        __syncthreads();

        // ---- A compute: 8b x 8n per thread ----
        u64 acc[8][4];
        #pragma unroll
        for (int j = 0; j < 8; j++)
            #pragma unroll
            for (int p = 0; p < 4; p++) acc[j][p] = 0ull;

        #pragma unroll 4
        for (int k = 0; k < 64; k++) {
            const float* ar = As + k*ASP + ty*8;
            float4 aA = *(const float4*)(ar);      // broadcast (2 addrs/warp)
            float4 aB = *(const float4*)(ar + 4);
            const float* wr = Ws + k*128 + tx*4;
            ulonglong2 w01 = *(const ulonglong2*)(wr);        // conflict-free
            ulonglong2 w23 = *(const ulonglong2*)(wr + 64);
            u64 a;
            a = pack2s(aA.x);
            acc[0][0] = fma2(a, w01.x, acc[0][0]);
            acc[0][1] = fma2(a, w01.y, acc[0][1]);
            acc[0][2] = fma2(a, w23.x, acc[0][2]);
            acc[0][3] = fma2(a, w23.y, acc[0][3]);
            a = pack2s(aA.y);
            acc[1][0] = fma2(a, w01.x, acc[1][0]);
            acc[1][1] = fma2(a, w01.y, acc[1][1]);
            acc[1][2] = fma2(a, w23.x, acc[1][2]);
            acc[1][3] = fma2(a, w23.y, acc[1][3]);
            a = pack2s(aA.z);
            acc[2][0] = fma2(a, w01.x, acc[2][0]);
            acc[2][1] = fma2(a, w01.y, acc[2][1]);
            acc[2][2] = fma2(a, w23.x, acc[2][2]);
            acc[2][3] = fma2(a, w23.y, acc[2][3]);
            a = pack2s(aA.w);
            acc[3][0] = fma2(a, w01.x, acc[3][0]);
            acc[3][1] = fma2(a, w01.y, acc[3][1]);
            acc[3][2] = fma2(a, w23.x, acc[3][2]);
            acc[3][3] = fma2(a, w23.y, acc[3][3]);
            a = pack2s(aB.x);
            acc[4][0] = fma2(a, w01.x, acc[4][0]);
            acc[4][1] = fma2(a, w01.y, acc[4][1]);
            acc[4][2] = fma2(a, w23.x, acc[4][2]);
            acc[4][3] = fma2(a, w23.y, acc[4][3]);
            a = pack2s(aB.y);
            acc[5][0] = fma2(a, w01.x, acc[5][0]);
            acc[5][1] = fma2(a, w01.y, acc[5][1]);
            acc[5][2] = fma2(a, w23.x, acc[5][2]);
            acc[5][3] = fma2(a, w23.y, acc[5][3]);
            a = pack2s(aB.z);
            acc[6][0] = fma2(a, w01.x, acc[6][0]);
            acc[6][1] = fma2(a, w01.y, acc[6][1]);
            acc[6][2] = fma2(a, w23.x, acc[6][2]);
            acc[6][3] = fma2(a, w23.y, acc[6][3]);
            a = pack2s(aB.w);
            acc[7][0] = fma2(a, w01.x, acc[7][0]);
            acc[7][1] = fma2(a, w01.y, acc[7][1]);
            acc[7][2] = fma2(a, w23.x, acc[7][2]);
            acc[7][3] = fma2(a, w23.y, acc[7][3]);
        }

        // ---- store partials (cols tx*4 and 64+tx*4) ----
        #pragma unroll
        for (int j = 0; j < 8; j++) {
            float* dst = &g_part[kc][(size_t)(ty*8 + j)*HH + nt*128 + tx*4];
            ulonglong2 v0; v0.x = acc[j][0]; v0.y = acc[j][1];
            ulonglong2 v1; v1.x = acc[j][2]; v1.y = acc[j][3];
            *(ulonglong2*)(dst)      = v0;
            *(ulonglong2*)(dst + 64) = v1;
        }

        // prefetch pre for B-role (independent of partials)
        float4 pre4 = *(const float4*)&g_pre[(size_t)s*BH + o];

        grid_sync();    // all partials(s) visible

        // ---- B reduce + tanh + write h_s (out coalesced, hT scattered) ----
        {
            float4 a4 = pre4;
            #pragma unroll
            for (int kk = 0; kk < KC; kk++) {
                float4 p = __ldcg((const float4*)&g_part[kk][o]);
                a4.x += p.x; a4.y += p.y; a4.z += p.z; a4.w += p.w;
            }
            float4 h = make_float4(tanh_fast(a4.x), tanh_fast(a4.y),
                                   tanh_fast(a4.z), tanh_fast(a4.w));
            *(float4*)&out[(size_t)s*BH + o] = h;
            float* hT = &g_hT[s & 1][0];
            hT[(oc+0)*BB + ob] = h.x;
            hT[(oc+1)*BB + ob] = h.y;
            hT[(oc+2)*BB + ob] = h.z;
            hT[(oc+3)*BB + ob] = h.w;
            hlast = h;
        }

        grid_sync();    // h_s (hT) visible; also guards partial-buffer WAR
    }

    // h_final: values this thread computed at s=511
    *(float4*)&out[(size_t)SS*BH + o] = hlast;
}

// =================================================================================
// Launch
// =================================================================================
extern "C" void kernel_launch(void* const* d_in, const int* in_sizes, int n_in,
                              void* d_out, int out_size) {
    const float* x  = (const float*)d_in[0];   // (S,B,I)
    const float* Ww = (const float*)d_in[1];   // (H,H)
    const float* Wb = (const float*)d_in[2];   // (H)
    const float* Vw = (const float*)d_in[3];   // (H,I)
    const float* Vb = (const float*)d_in[4];   // (H)
    float* out = (float*)d_out;                // (S,B,H) then (1,B,H)

    dim3 g1(256, 8);
    pre_gemm_kernel<<<g1, 256>>>(x, Vw, Wb, Vb);

    static int smem_set = 0;
    const int smem_bytes = (64*128 + 64*ASP) * (int)sizeof(float);  // 50176
    if (!smem_set) {
        cudaFuncSetAttribute(rnn_recurrent_kernel,
                             cudaFuncAttributeMaxDynamicSharedMemorySize, smem_bytes);
        smem_set = 1;
    }
    rnn_recurrent_kernel<<<NB, 128, smem_bytes>>>(Ww, out);
}